// round 7
// baseline (speedup 1.0000x reference)
#include <cuda_runtime.h>
#include <stdint.h>

// Problem constants
#define BB 4
#define TT 2048
#define DD 768
#define HH 12
#define HD 64

#define M1 (BB*TT)      // 8192
#define N1 (3*DD)       // 2304
#define K1 DD           // 768

// Scratch (alloc-free). All values pre-rounded to tf32 so MMA RZ truncation
// is lossless.
__device__ float g_q[BB*HH*TT*HD];
__device__ float g_k[BB*HH*TT*HD];
__device__ float g_v[BB*HH*TT*HD];
__device__ float g_attn[BB*TT*DD];
__device__ float g_xr[M1*K1];
__device__ float g_wqkv[K1*N1];
__device__ float g_wout[DD*DD];

// ---------------------------------------------------------------------------
__device__ __forceinline__ uint32_t tf32_of(float x) {
    uint32_t u;
    asm("cvt.rna.tf32.f32 %0, %1;" : "=r"(u) : "f"(x));
    return u;
}

__device__ __forceinline__ void mma8(float* c,
                                     const uint32_t* a,
                                     const uint32_t* b) {
    asm volatile(
        "mma.sync.aligned.m16n8k8.row.col.f32.tf32.tf32.f32 "
        "{%0,%1,%2,%3}, {%4,%5,%6,%7}, {%8,%9}, {%0,%1,%2,%3};\n"
        : "+f"(c[0]), "+f"(c[1]), "+f"(c[2]), "+f"(c[3])
        : "r"(a[0]), "r"(a[1]), "r"(a[2]), "r"(a[3]),
          "r"(b[0]), "r"(b[1]));
}

__device__ __forceinline__ void cp16(uint32_t smem_dst, const void* gsrc) {
    asm volatile("cp.async.ca.shared.global [%0], [%1], 16;\n"
                 :: "r"(smem_dst), "l"(gsrc));
}
#define CP_COMMIT() asm volatile("cp.async.commit_group;\n" ::: "memory")
#define CP_WAIT(N)  asm volatile("cp.async.wait_group %0;\n" :: "n"(N) : "memory")

// ---------------------------------------------------------------------------
__global__ void round_tf32_kernel(const float* __restrict__ in,
                                  float* __restrict__ out, int n4) {
    int i = blockIdx.x * blockDim.x + threadIdx.x;
    if (i < n4) {
        float4 v = ((const float4*)in)[i];
        float4 r;
        r.x = __uint_as_float(tf32_of(v.x));
        r.y = __uint_as_float(tf32_of(v.y));
        r.z = __uint_as_float(tf32_of(v.z));
        r.w = __uint_as_float(tf32_of(v.w));
        ((float4*)out)[i] = r;
    }
}

// ---------------------------------------------------------------------------
// Tensor-core GEMM: CTA tile 128x256, k-chunk 32, 256 threads / 8 warps
// (2 warp_m x 4 warp_n), warp tile 64x64 (mf=4, nf=8). cp.async 2-stage.
// MODE 0: scatter rounded into g_q (x0.125) / g_k / g_v (+bias)
// MODE 1: C row-major (+bias)
// ---------------------------------------------------------------------------
#define AP 36
#define BPg 264
#define ASW (128*AP)     // 4608 words per A stage
#define BSW (32*BPg)     // 8448 words per B stage

template<int MODE>
__global__ __launch_bounds__(256, 1) void gemm_tc(
    const float* __restrict__ A,
    const float* __restrict__ Bm,
    const float* __restrict__ bias,
    float* __restrict__ C,
    int M, int N, int K)
{
    extern __shared__ float smg[];
    uint32_t* su = (uint32_t*)smg;
    const uint32_t sbase = (uint32_t)__cvta_generic_to_shared(smg);

    const int tid = threadIdx.x;
    const int w = tid >> 5;
    const int lane = tid & 31;
    const int g = lane >> 2;
    const int tig = lane & 3;
    const int warp_m = w >> 2;      // 0..1
    const int warp_n = w & 3;       // 0..3
    const int row0 = blockIdx.y * 128;
    const int col0 = blockIdx.x * 256;

    float acc[4][8][4];
    #pragma unroll
    for (int mf = 0; mf < 4; mf++)
        #pragma unroll
        for (int nf = 0; nf < 8; nf++)
            #pragma unroll
            for (int e = 0; e < 4; e++) acc[mf][nf][e] = 0.f;

    auto issue_tile = [&](int s, int k0) {
        uint32_t abase = sbase + (s * ASW) * 4;
        #pragma unroll
        for (int l = 0; l < 4; l++) {
            int id = tid + l * 256;
            int r = id >> 3;
            int c = (id & 7) << 2;
            cp16(abase + (r * AP + c) * 4, A + (long)(row0 + r) * K + k0 + c);
        }
        uint32_t bbase = sbase + (2 * ASW + s * BSW) * 4;
        #pragma unroll
        for (int l = 0; l < 8; l++) {
            int id = tid + l * 256;
            int r = id >> 6;             // 0..31
            int c = (id & 63) << 2;      // 0..252
            cp16(bbase + (r * BPg + c) * 4, Bm + (long)(k0 + r) * N + col0 + c);
        }
    };

    const int ntiles = K / 32;
    issue_tile(0, 0);
    CP_COMMIT();

    for (int t = 0; t < ntiles; t++) {
        if (t + 1 < ntiles) {
            issue_tile((t + 1) & 1, (t + 1) * 32);
            CP_COMMIT();
            CP_WAIT(1);
        } else {
            CP_WAIT(0);
        }
        __syncthreads();

        const uint32_t* As = su + (t & 1) * ASW;
        const uint32_t* Bs = su + 2 * ASW + (t & 1) * BSW;

        #pragma unroll
        for (int ks = 0; ks < 4; ks++) {
            const int kc = ks * 8;
            uint32_t bf[8][2];
            #pragma unroll
            for (int nf = 0; nf < 8; nf++) {
                int cn = warp_n * 64 + nf * 8 + g;
                bf[nf][0] = Bs[(kc + tig) * BPg + cn];
                bf[nf][1] = Bs[(kc + tig + 4) * BPg + cn];
            }
            uint32_t af[4][4];
            #pragma unroll
            for (int mf = 0; mf < 4; mf++) {
                int r0i = (warp_m * 64 + mf * 16 + g) * AP;
                int r1i = r0i + 8 * AP;
                af[mf][0] = As[r0i + kc + tig];
                af[mf][1] = As[r1i + kc + tig];
                af[mf][2] = As[r0i + kc + tig + 4];
                af[mf][3] = As[r1i + kc + tig + 4];
            }
            #pragma unroll
            for (int mf = 0; mf < 4; mf++)
                #pragma unroll
                for (int nf = 0; nf < 8; nf++)
                    mma8(acc[mf][nf], af[mf], bf[nf]);
        }
        __syncthreads();
    }

    // Epilogue — paired float2 stores
    #pragma unroll
    for (int mf = 0; mf < 4; mf++) {
        #pragma unroll
        for (int nf = 0; nf < 8; nf++) {
            #pragma unroll
            for (int eh = 0; eh < 2; eh++) {
                int r = row0 + warp_m * 64 + mf * 16 + g + (eh << 3);
                int c = col0 + warp_n * 64 + nf * 8 + 2 * tig;
                float v0 = acc[mf][nf][2 * eh]     + bias[c];
                float v1 = acc[mf][nf][2 * eh + 1] + bias[c + 1];
                if (MODE == 0) {
                    int sec = c / DD;            // constant within the pair
                    int d = c - sec * DD;
                    int hh = d >> 6;
                    int di = d & 63;
                    int bb = r >> 11;
                    int tt = r & 2047;
                    int off = (((bb * HH + hh) * TT) + tt) * HD + di;
                    float2 p;
                    if (sec == 0) {
                        p.x = __uint_as_float(tf32_of(v0 * 0.125f));
                        p.y = __uint_as_float(tf32_of(v1 * 0.125f));
                        *(float2*)(g_q + off) = p;
                    } else if (sec == 1) {
                        p.x = __uint_as_float(tf32_of(v0));
                        p.y = __uint_as_float(tf32_of(v1));
                        *(float2*)(g_k + off) = p;
                    } else {
                        p.x = __uint_as_float(tf32_of(v0));
                        p.y = __uint_as_float(tf32_of(v1));
                        *(float2*)(g_v + off) = p;
                    }
                } else {
                    float2 p = make_float2(v0, v1);
                    *(float2*)(C + (long)r * N + c) = p;
                }
            }
        }
    }
}

// ---------------------------------------------------------------------------
// Flash attention: CTA = (b, h, 128-row q block), 128 threads / 4 warps,
// warp owns 32 q-rows (mf=2). Q fully in registers; P reuses Q smem region
// (warp-private rows). K-tiles of 64 tokens, cp.async double-buffered.
//   P/Q pitch 68 (A-frag banks), Ks pitch 68 (B-frag), Vs pitch 72 (B-frag).
// ---------------------------------------------------------------------------
#define QP 68
#define VP 72
#define PQ_OFF 0
#define KS_OFF (128*QP)                 // 8704
#define KSW (64*QP)                     // 4352 per stage
#define VS_OFF (KS_OFF + 2*KSW)        // 17408
#define VSW (64*VP)                     // 4608 per stage
#define SMW (VS_OFF + 2*VSW)           // 26624 words = 106496 B

__global__ __launch_bounds__(128, 2) void attn_tc()
{
    extern __shared__ float sma[];
    uint32_t* su = (uint32_t*)sma;
    const uint32_t sbase = (uint32_t)__cvta_generic_to_shared(sma);

    const int tid = threadIdx.x;
    const int w = tid >> 5;              // 0..3
    const int lane = tid & 31;
    const int g = lane >> 2;
    const int tig = lane & 3;
    const int qb = blockIdx.x;           // 0..15
    const int h  = blockIdx.y;
    const int bb = blockIdx.z;

    const int bh = bb * HH + h;
    const float* Qg = g_q + ((long)bh * TT + qb * 128) * HD;
    const float* Kg = g_k + (long)bh * TT * HD;
    const float* Vg = g_v + (long)bh * TT * HD;

    auto issue_kv = [&](int s, int kt) {
        const float* Kt = Kg + kt * 64 * HD;
        const float* Vt = Vg + kt * 64 * HD;
        uint32_t kb = sbase + (KS_OFF + s * KSW) * 4;
        uint32_t vb = sbase + (VS_OFF + s * VSW) * 4;
        #pragma unroll
        for (int l = 0; l < 8; l++) {
            int id = tid + l * 128;
            int r = id >> 4;             // 0..63
            int c = (id & 15) << 2;
            cp16(kb + (r * QP + c) * 4, Kt + r * HD + c);
            cp16(vb + (r * VP + c) * 4, Vt + r * HD + c);
        }
    };

    // Prologue: Q (into PQ region) + tile0
    {
        uint32_t qdst = sbase + PQ_OFF * 4;
        #pragma unroll
        for (int l = 0; l < 16; l++) {
            int id = tid + l * 128;
            int r = id >> 4;             // 0..127
            int c = (id & 15) << 2;
            cp16(qdst + (r * QP + c) * 4, Qg + r * HD + c);
        }
        issue_kv(0, 0);
        CP_COMMIT();
        CP_WAIT(0);
        __syncthreads();
    }

    // Preload Q fragments to registers (warp-private rows), then P may
    // overwrite the region.
    uint32_t qa[2][8][4];
    #pragma unroll
    for (int mf = 0; mf < 2; mf++) {
        int r0i = PQ_OFF + (w * 32 + mf * 16 + g) * QP;
        int r1i = r0i + 8 * QP;
        #pragma unroll
        for (int ks = 0; ks < 8; ks++) {
            const int kc = ks * 8;
            qa[mf][ks][0] = su[r0i + kc + tig];
            qa[mf][ks][1] = su[r1i + kc + tig];
            qa[mf][ks][2] = su[r0i + kc + tig + 4];
            qa[mf][ks][3] = su[r1i + kc + tig + 4];
        }
    }
    __syncwarp();

    float o[2][8][4];
    #pragma unroll
    for (int mf = 0; mf < 2; mf++)
        #pragma unroll
        for (int nf = 0; nf < 8; nf++)
            #pragma unroll
            for (int e = 0; e < 4; e++) o[mf][nf][e] = 0.f;
    float mrow[2][2] = {{-1e30f, -1e30f}, {-1e30f, -1e30f}};
    float lrow[2][2] = {{0.f, 0.f}, {0.f, 0.f}};

    for (int kt = 0; kt < TT / 64; kt++) {
        if (kt + 1 < TT / 64) {
            issue_kv((kt + 1) & 1, kt + 1);
            CP_COMMIT();
            CP_WAIT(1);
        } else {
            CP_WAIT(0);
        }
        __syncthreads();

        const uint32_t* Ks = su + KS_OFF + (kt & 1) * KSW;
        const uint32_t* Vs = su + VS_OFF + (kt & 1) * VSW;

        // S = Q @ K^T (both mf share each K fragment)
        float s[2][8][4];
        #pragma unroll
        for (int mf = 0; mf < 2; mf++)
            #pragma unroll
            for (int nf = 0; nf < 8; nf++)
                #pragma unroll
                for (int e = 0; e < 4; e++) s[mf][nf][e] = 0.f;

        #pragma unroll
        for (int ks = 0; ks < 8; ks++) {
            const int kc = ks * 8;
            #pragma unroll
            for (int nf = 0; nf < 8; nf++) {
                uint32_t kb[2];
                int rowi = (nf * 8 + g) * QP;
                kb[0] = Ks[rowi + kc + tig];
                kb[1] = Ks[rowi + kc + tig + 4];
                mma8(s[0][nf], qa[0][ks], kb);
                mma8(s[1][nf], qa[1][ks], kb);
            }
        }

        // Online softmax + P write (per mf; rows are warp-private)
        #pragma unroll
        for (int mf = 0; mf < 2; mf++) {
            float rm0 = -1e30f, rm1 = -1e30f;
            #pragma unroll
            for (int nf = 0; nf < 8; nf++) {
                rm0 = fmaxf(rm0, fmaxf(s[mf][nf][0], s[mf][nf][1]));
                rm1 = fmaxf(rm1, fmaxf(s[mf][nf][2], s[mf][nf][3]));
            }
            #pragma unroll
            for (int off = 1; off <= 2; off <<= 1) {
                rm0 = fmaxf(rm0, __shfl_xor_sync(0xffffffffu, rm0, off));
                rm1 = fmaxf(rm1, __shfl_xor_sync(0xffffffffu, rm1, off));
            }
            float mn0 = fmaxf(mrow[mf][0], rm0);
            float mn1 = fmaxf(mrow[mf][1], rm1);
            float al0 = __expf(mrow[mf][0] - mn0);
            float al1 = __expf(mrow[mf][1] - mn1);
            mrow[mf][0] = mn0; mrow[mf][1] = mn1;
            float rs0 = 0.f, rs1 = 0.f;
            #pragma unroll
            for (int nf = 0; nf < 8; nf++) {
                s[mf][nf][0] = __expf(s[mf][nf][0] - mn0);
                s[mf][nf][1] = __expf(s[mf][nf][1] - mn0);
                s[mf][nf][2] = __expf(s[mf][nf][2] - mn1);
                s[mf][nf][3] = __expf(s[mf][nf][3] - mn1);
                rs0 += s[mf][nf][0] + s[mf][nf][1];
                rs1 += s[mf][nf][2] + s[mf][nf][3];
            }
            #pragma unroll
            for (int off = 1; off <= 2; off <<= 1) {
                rs0 += __shfl_xor_sync(0xffffffffu, rs0, off);
                rs1 += __shfl_xor_sync(0xffffffffu, rs1, off);
            }
            lrow[mf][0] = lrow[mf][0] * al0 + rs0;
            lrow[mf][1] = lrow[mf][1] * al1 + rs1;
            #pragma unroll
            for (int nf = 0; nf < 8; nf++) {
                o[mf][nf][0] *= al0; o[mf][nf][1] *= al0;
                o[mf][nf][2] *= al1; o[mf][nf][3] *= al1;
            }
            // P write: STS.64 pairs (tf32-rounded)
            int pr0 = PQ_OFF + (w * 32 + mf * 16 + g) * QP;
            int pr1 = pr0 + 8 * QP;
            #pragma unroll
            for (int nf = 0; nf < 8; nf++) {
                int cb = nf * 8 + 2 * tig;
                uint2 p0 = make_uint2(tf32_of(s[mf][nf][0]), tf32_of(s[mf][nf][1]));
                uint2 p1 = make_uint2(tf32_of(s[mf][nf][2]), tf32_of(s[mf][nf][3]));
                *(uint2*)&su[pr0 + cb] = p0;
                *(uint2*)&su[pr1 + cb] = p1;
            }
        }
        __syncwarp();

        // O += P @ V
        #pragma unroll
        for (int ks = 0; ks < 8; ks++) {
            const int kc = ks * 8;
            uint32_t pa[2][4];
            #pragma unroll
            for (int mf = 0; mf < 2; mf++) {
                int r0i = PQ_OFF + (w * 32 + mf * 16 + g) * QP;
                int r1i = r0i + 8 * QP;
                pa[mf][0] = su[r0i + kc + tig];
                pa[mf][1] = su[r1i + kc + tig];
                pa[mf][2] = su[r0i + kc + tig + 4];
                pa[mf][3] = su[r1i + kc + tig + 4];
            }
            #pragma unroll
            for (int nf = 0; nf < 8; nf++) {
                uint32_t vb[2];
                vb[0] = Vs[(kc + tig) * VP + nf * 8 + g];
                vb[1] = Vs[(kc + tig + 4) * VP + nf * 8 + g];
                mma8(o[0][nf], pa[0], vb);
                mma8(o[1][nf], pa[1], vb);
            }
        }
        __syncthreads();
    }

    // Normalized, tf32-rounded output into [b][t][h*64+d]
    float* Og = g_attn + ((long)bb * TT + qb * 128) * DD + h * HD;
    #pragma unroll
    for (int mf = 0; mf < 2; mf++) {
        float inv0 = 1.f / lrow[mf][0];
        float inv1 = 1.f / lrow[mf][1];
        int r0 = w * 32 + mf * 16 + g;
        #pragma unroll
        for (int nf = 0; nf < 8; nf++) {
            int cb = nf * 8 + 2 * tig;
            float2 p0, p1;
            p0.x = __uint_as_float(tf32_of(o[mf][nf][0] * inv0));
            p0.y = __uint_as_float(tf32_of(o[mf][nf][1] * inv0));
            p1.x = __uint_as_float(tf32_of(o[mf][nf][2] * inv1));
            p1.y = __uint_as_float(tf32_of(o[mf][nf][3] * inv1));
            *(float2*)(Og + (long)r0 * DD + cb) = p0;
            *(float2*)(Og + (long)(r0 + 8) * DD + cb) = p1;
        }
    }
}

// ---------------------------------------------------------------------------
extern "C" void kernel_launch(void* const* d_in, const int* in_sizes, int n_in,
                              void* d_out, int out_size)
{
    const float* x     = (const float*)d_in[0];
    const float* w_qkv = (const float*)d_in[1];
    const float* b_qkv = (const float*)d_in[2];
    const float* w_out = (const float*)d_in[3];
    const float* b_out = (const float*)d_in[4];
    float* out = (float*)d_out;

    (void)in_sizes; (void)n_in; (void)out_size;

    float *xr, *wqkvr, *woutr, *attn_ptr;
    cudaGetSymbolAddress((void**)&xr, g_xr);
    cudaGetSymbolAddress((void**)&wqkvr, g_wqkv);
    cudaGetSymbolAddress((void**)&woutr, g_wout);
    cudaGetSymbolAddress((void**)&attn_ptr, g_attn);

    // Pre-round inputs to tf32 (RNA)
    {
        int n4 = (M1 * K1) / 4;
        round_tf32_kernel<<<(n4 + 255) / 256, 256>>>(x, xr, n4);
        n4 = (K1 * N1) / 4;
        round_tf32_kernel<<<(n4 + 255) / 256, 256>>>(w_qkv, wqkvr, n4);
        n4 = (DD * DD) / 4;
        round_tf32_kernel<<<(n4 + 255) / 256, 256>>>(w_out, woutr, n4);
    }

    const int gemm_smem = (2 * ASW + 2 * BSW) * (int)sizeof(float); // 104448
    cudaFuncSetAttribute(gemm_tc<0>, cudaFuncAttributeMaxDynamicSharedMemorySize, gemm_smem);
    cudaFuncSetAttribute(gemm_tc<1>, cudaFuncAttributeMaxDynamicSharedMemorySize, gemm_smem);

    // QKV projection + scatter
    {
        dim3 grid(N1 / 256, M1 / 128);   // 9 x 64
        gemm_tc<0><<<grid, 256, gemm_smem>>>(xr, wqkvr, b_qkv, nullptr, M1, N1, K1);
    }

    // Flash attention
    {
        int smem_bytes = SMW * (int)sizeof(float);  // 106496
        cudaFuncSetAttribute(attn_tc, cudaFuncAttributeMaxDynamicSharedMemorySize, smem_bytes);
        dim3 grid(TT / 128, HH, BB);     // 16 x 12 x 4
        attn_tc<<<grid, 128, smem_bytes>>>();
    }

    // Output projection
    {
        dim3 grid(DD / 256, M1 / 128);   // 3 x 64
        gemm_tc<1><<<grid, 256, gemm_smem>>>(attn_ptr, woutr, b_out, out, M1, DD, DD);
    }
}